// round 6
// baseline (speedup 1.0000x reference)
#include <cuda_runtime.h>
#include <math.h>

// ---------------------------------------------------------------------------
// ZBLRepulsion: per-edge repulsion energy + segment_sum over receivers.
//   N_NODES = 1,000,000   N_EDGES = 32,000,000   N_SPECIES = 100
//
// Floor (validated R3-R5): ~100M l1tex wavefronts (64M random species gathers
// + 32M spread RED + 4M streaming) -> L1=87%, L2=89% co-saturated at 337us.
// This round: wave balancing. 4 edges/thread = 8M threads = 0.85 waves ->
// tail-spread exposed. 1 edge/thread = 32M threads = ~3.3 waves; identical
// per-edge wavefront cost (scalar streams coalesce to the same lines).
// ---------------------------------------------------------------------------

#define KE_CONST 14.399645351950548
#define MAX_NODES   1000000
#define MAX_SPECIES 128

__device__ float  g_params[8];                      // a0..a3, c0..3 (*KE/2)
__device__ float2 g_stab[MAX_SPECIES];              // per-species {z, d*z^p}
__device__ uchar4 g_spec4[(MAX_NODES + 3) / 4];     // packed species bytes

__device__ __forceinline__ float softplus_f(float x) {
    return fmaxf(x, 0.0f) + log1pf(expf(-fabsf(x)));
}

// ---- kernel 0: fused prep (params+table in block 0; pack+zero everywhere) --
__global__ void zbl_prep_kernel(const float* __restrict__ a_raw,
                                const float* __restrict__ c_raw,
                                const float* __restrict__ p_raw,
                                const float* __restrict__ d_raw,
                                const int* __restrict__ index_to_z,
                                const int* __restrict__ species,
                                float* __restrict__ out,
                                int n_species, int n_nodes, int out_n) {
    if (blockIdx.x == 0) {
        int t = threadIdx.x;
        if (t < n_species) {
            float p  = softplus_f(p_raw[0]);
            float d  = softplus_f(d_raw[0]);
            float zf = (float)index_to_z[t];
            g_stab[t] = make_float2(zf, d * powf(zf, p));
        }
        if (t == 0) {
            float c[4], csum = 0.0f;
#pragma unroll
            for (int k = 0; k < 4; k++) {
                g_params[k] = softplus_f(a_raw[k]);
                c[k] = softplus_f(c_raw[k]);
                csum += c[k];
            }
            float scale = (float)(KE_CONST * 0.5) / csum;
#pragma unroll
            for (int k = 0; k < 4; k++) g_params[4 + k] = c[k] * scale;
        }
    }

    int q = blockIdx.x * blockDim.x + threadIdx.x;
    int base = q * 4;
    if (base + 3 < n_nodes) {
        int4 s = *reinterpret_cast<const int4*>(species + base);
        g_spec4[q] = make_uchar4((unsigned char)s.x, (unsigned char)s.y,
                                 (unsigned char)s.z, (unsigned char)s.w);
    } else if (base < n_nodes) {
        unsigned char* sp = reinterpret_cast<unsigned char*>(g_spec4);
        for (int k = base; k < n_nodes; k++) sp[k] = (unsigned char)species[k];
    }
    if (base + 3 < out_n) {
        *reinterpret_cast<float4*>(out + base) = make_float4(0.f, 0.f, 0.f, 0.f);
    } else if (base < out_n) {
        for (int k = base; k < out_n; k++) out[k] = 0.0f;
    }
}

// ---- per-edge math (proven R2 body) ---------------------------------------
__device__ __forceinline__ float zbl_energy(float dd, float ct,
                                            unsigned int si, unsigned int ri,
                                            const float* __restrict__ P,
                                            const float2* __restrict__ stab) {
    float2 nj = stab[si];
    float2 ni = stab[ri];

    float x   = ct * ni.x * nj.x * __fdividef(1.0f, dd + 1e-8f);
    float rzd = dd * (ni.y + nj.y);

    float y = P[4] * __expf(-P[0] * rzd)
            + P[5] * __expf(-P[1] * rzd)
            + P[6] * __expf(-P[2] * rzd)
            + P[7] * __expf(-P[3] * rzd);

    float sd = dd * (1.0f / 1.5f);
    float e1 = __expf(-__fdividef(1.0f, fmaxf(sd, 1e-8f)));
    float e2 = __expf(-__fdividef(1.0f, fmaxf(1.0f - sd, 1e-8f)));
    float w  = __fdividef(e2, e1 + e2);

    return w * x * y;
}

// ---- kernel 1: edge loop, 1 edge/thread -----------------------------------
__global__ void __launch_bounds__(256)
zbl_edge_kernel(const float* __restrict__ distances,
                const float* __restrict__ cutoffs,
                const int* __restrict__ senders,
                const int* __restrict__ receivers,
                float* __restrict__ out,
                int n_edges, int n_species) {
    __shared__ float2 stab[MAX_SPECIES];
    for (int t = threadIdx.x; t < n_species; t += blockDim.x)
        stab[t] = g_stab[t];
    float P[8];
#pragma unroll
    for (int k = 0; k < 8; k++) P[k] = g_params[k];
    __syncthreads();

    const unsigned char* spec = reinterpret_cast<const unsigned char*>(g_spec4);

    int e = blockIdx.x * blockDim.x + threadIdx.x;
    if (e >= n_edges) return;

    // coalesced scalar streams (L2-only), then the two random gathers
    float dd = __ldcg(distances + e);
    float ct = __ldcg(cutoffs + e);
    int   s  = __ldcg(senders + e);
    int   r  = __ldcg(receivers + e);

    unsigned int si = __ldg(spec + s);
    unsigned int ri = __ldg(spec + r);

    float v = zbl_energy(dd, ct, si, ri, P, stab);
    atomicAdd(out + r, v);                 // no return use -> RED.ADD
}

// ---------------------------------------------------------------------------
extern "C" void kernel_launch(void* const* d_in, const int* in_sizes, int n_in,
                              void* d_out, int out_size) {
    const int*   node_species = (const int*)  d_in[0];
    const float* distances    = (const float*)d_in[1];
    const float* cutoffs      = (const float*)d_in[2];
    const int*   senders      = (const int*)  d_in[3];
    const int*   receivers    = (const int*)  d_in[4];
    const int*   index_to_z   = (const int*)  d_in[5];
    const float* a_raw        = (const float*)d_in[6];
    const float* c_raw        = (const float*)d_in[7];
    const float* p_raw        = (const float*)d_in[8];
    const float* d_raw        = (const float*)d_in[9];

    int n_nodes   = in_sizes[0];
    int n_edges   = in_sizes[1];
    int n_species = in_sizes[5];
    float* out    = (float*)d_out;

    {
        int n = (n_nodes > out_size) ? n_nodes : out_size;
        int quads   = (n + 3) / 4;
        int threads = 256;
        int blocks  = (quads + threads - 1) / threads;
        zbl_prep_kernel<<<blocks, threads>>>(a_raw, c_raw, p_raw, d_raw,
                                             index_to_z, node_species, out,
                                             n_species, n_nodes, out_size);
    }

    {
        int threads = 256;
        int blocks  = (n_edges + threads - 1) / threads;
        zbl_edge_kernel<<<blocks, threads>>>(distances, cutoffs, senders,
                                             receivers, out, n_edges,
                                             n_species);
    }
}

// round 7
// speedup vs baseline: 1.0827x; 1.0827x over previous
#include <cuda_runtime.h>
#include <math.h>

// ---------------------------------------------------------------------------
// ZBLRepulsion: per-edge repulsion energy + segment_sum over receivers.
//   N_NODES = 1,000,000   N_EDGES = 32,000,000   N_SPECIES = 100
//
// Converged design (R5, best measured 334.8us):
//   prep : params + 100-entry species table (block 0); species->u8 pack;
//          zero output.  (2 launches/call total)
//   edge : 4 edges/thread, float4/int4 L2-streaming loads, 8 batched random
//          u8 species gathers (1MB table, L1-cacheable), smem species->
//          {z, d*z^p} resolve, RED.ADD scatter into out.
//
// Floor model (validated R3-R6): l1tex wavefronts are binding —
//   64M random gather lanes + 32M spread REDG + 4M streaming ≈ 676K cyc/SM.
// Controlling variable is per-thread gather MLP at exactly 32 regs
// (64-warp occupancy): 1/thr and 8/thr both measurably worse; carveout
// attributes and exp-count rewrites both measurably worse. Alternatives
// (DSMEM cluster table, sorting, binned scatter, edge-precompute) all
// re-spend the wavefronts they save.
// ---------------------------------------------------------------------------

#define KE_CONST 14.399645351950548
#define MAX_NODES   1000000
#define MAX_SPECIES 128

__device__ float  g_params[8];                      // a0..a3, c0..3 (*KE/2)
__device__ float2 g_stab[MAX_SPECIES];              // per-species {z, d*z^p}
__device__ uchar4 g_spec4[(MAX_NODES + 3) / 4];     // packed species bytes

__device__ __forceinline__ float softplus_f(float x) {
    return fmaxf(x, 0.0f) + log1pf(expf(-fabsf(x)));
}

// ---- kernel 0: fused prep (params+table in block 0; pack+zero everywhere) --
__global__ void zbl_prep_kernel(const float* __restrict__ a_raw,
                                const float* __restrict__ c_raw,
                                const float* __restrict__ p_raw,
                                const float* __restrict__ d_raw,
                                const int* __restrict__ index_to_z,
                                const int* __restrict__ species,
                                float* __restrict__ out,
                                int n_species, int n_nodes, int out_n) {
    if (blockIdx.x == 0) {
        int t = threadIdx.x;
        if (t < n_species) {
            float p  = softplus_f(p_raw[0]);
            float d  = softplus_f(d_raw[0]);
            float zf = (float)index_to_z[t];
            g_stab[t] = make_float2(zf, d * powf(zf, p));
        }
        if (t == 0) {
            float c[4], csum = 0.0f;
#pragma unroll
            for (int k = 0; k < 4; k++) {
                g_params[k] = softplus_f(a_raw[k]);
                c[k] = softplus_f(c_raw[k]);
                csum += c[k];
            }
            float scale = (float)(KE_CONST * 0.5) / csum;
#pragma unroll
            for (int k = 0; k < 4; k++) g_params[4 + k] = c[k] * scale;
        }
    }

    int q = blockIdx.x * blockDim.x + threadIdx.x;
    int base = q * 4;
    if (base + 3 < n_nodes) {
        int4 s = *reinterpret_cast<const int4*>(species + base);
        g_spec4[q] = make_uchar4((unsigned char)s.x, (unsigned char)s.y,
                                 (unsigned char)s.z, (unsigned char)s.w);
    } else if (base < n_nodes) {
        unsigned char* sp = reinterpret_cast<unsigned char*>(g_spec4);
        for (int k = base; k < n_nodes; k++) sp[k] = (unsigned char)species[k];
    }
    if (base + 3 < out_n) {
        *reinterpret_cast<float4*>(out + base) = make_float4(0.f, 0.f, 0.f, 0.f);
    } else if (base < out_n) {
        for (int k = base; k < out_n; k++) out[k] = 0.0f;
    }
}

// ---- per-edge math --------------------------------------------------------
__device__ __forceinline__ float zbl_energy(float dd, float ct,
                                            unsigned int si, unsigned int ri,
                                            const float* __restrict__ P,
                                            const float2* __restrict__ stab) {
    float2 nj = stab[si];
    float2 ni = stab[ri];

    float x   = ct * ni.x * nj.x * __fdividef(1.0f, dd + 1e-8f);
    float rzd = dd * (ni.y + nj.y);

    float y = P[4] * __expf(-P[0] * rzd)
            + P[5] * __expf(-P[1] * rzd)
            + P[6] * __expf(-P[2] * rzd)
            + P[7] * __expf(-P[3] * rzd);

    float sd = dd * (1.0f / 1.5f);
    float e1 = __expf(-__fdividef(1.0f, fmaxf(sd, 1e-8f)));
    float e2 = __expf(-__fdividef(1.0f, fmaxf(1.0f - sd, 1e-8f)));
    float w  = __fdividef(e2, e1 + e2);

    return w * x * y;
}

// ---- kernel 1: edge loop, 4 edges/thread (empirical optimum, 32 regs) -----
__global__ void __launch_bounds__(256)
zbl_edge_kernel(const float* __restrict__ distances,
                const float* __restrict__ cutoffs,
                const int* __restrict__ senders,
                const int* __restrict__ receivers,
                float* __restrict__ out,
                int n_edges, int n_species) {
    __shared__ float2 stab[MAX_SPECIES];
    for (int t = threadIdx.x; t < n_species; t += blockDim.x)
        stab[t] = g_stab[t];
    float P[8];
#pragma unroll
    for (int k = 0; k < 8; k++) P[k] = g_params[k];
    __syncthreads();

    const unsigned char* spec = reinterpret_cast<const unsigned char*>(g_spec4);

    int i  = blockIdx.x * blockDim.x + threadIdx.x;
    long long e0 = (long long)i * 4;
    if (e0 >= n_edges) return;

    if (e0 + 3 < n_edges) {
        // streaming loads: L2-only, keep L1 for the species gathers
        float4 d4 = __ldcg(reinterpret_cast<const float4*>(distances + e0));
        float4 c4 = __ldcg(reinterpret_cast<const float4*>(cutoffs   + e0));
        int4   s4 = __ldcg(reinterpret_cast<const int4*>(senders    + e0));
        int4   r4 = __ldcg(reinterpret_cast<const int4*>(receivers  + e0));

        // all 8 gathers in flight before compute
        unsigned int sa = __ldg(spec + s4.x), ra = __ldg(spec + r4.x);
        unsigned int sb = __ldg(spec + s4.y), rb = __ldg(spec + r4.y);
        unsigned int sc = __ldg(spec + s4.z), rc = __ldg(spec + r4.z);
        unsigned int sd_ = __ldg(spec + s4.w), rd = __ldg(spec + r4.w);

        float va = zbl_energy(d4.x, c4.x, sa, ra, P, stab);
        float vb = zbl_energy(d4.y, c4.y, sb, rb, P, stab);
        float vc = zbl_energy(d4.z, c4.z, sc, rc, P, stab);
        float vd = zbl_energy(d4.w, c4.w, sd_, rd, P, stab);

        atomicAdd(out + r4.x, va);
        atomicAdd(out + r4.y, vb);
        atomicAdd(out + r4.z, vc);
        atomicAdd(out + r4.w, vd);
    } else {
        for (long long e = e0; e < n_edges; e++) {
            unsigned int si = spec[senders[e]];
            unsigned int ri = spec[receivers[e]];
            float v = zbl_energy(distances[e], cutoffs[e], si, ri, P, stab);
            atomicAdd(out + receivers[e], v);
        }
    }
}

// ---------------------------------------------------------------------------
extern "C" void kernel_launch(void* const* d_in, const int* in_sizes, int n_in,
                              void* d_out, int out_size) {
    const int*   node_species = (const int*)  d_in[0];
    const float* distances    = (const float*)d_in[1];
    const float* cutoffs      = (const float*)d_in[2];
    const int*   senders      = (const int*)  d_in[3];
    const int*   receivers    = (const int*)  d_in[4];
    const int*   index_to_z   = (const int*)  d_in[5];
    const float* a_raw        = (const float*)d_in[6];
    const float* c_raw        = (const float*)d_in[7];
    const float* p_raw        = (const float*)d_in[8];
    const float* d_raw        = (const float*)d_in[9];

    int n_nodes   = in_sizes[0];
    int n_edges   = in_sizes[1];
    int n_species = in_sizes[5];
    float* out    = (float*)d_out;

    {
        int n = (n_nodes > out_size) ? n_nodes : out_size;
        int quads   = (n + 3) / 4;
        int threads = 256;
        int blocks  = (quads + threads - 1) / threads;
        zbl_prep_kernel<<<blocks, threads>>>(a_raw, c_raw, p_raw, d_raw,
                                             index_to_z, node_species, out,
                                             n_species, n_nodes, out_size);
    }

    {
        int threads = 256;
        long long quads = ((long long)n_edges + 3) / 4;
        int blocks  = (int)((quads + threads - 1) / threads);
        zbl_edge_kernel<<<blocks, threads>>>(distances, cutoffs, senders,
                                             receivers, out, n_edges,
                                             n_species);
    }
}

// round 8
// speedup vs baseline: 1.0984x; 1.0145x over previous
#include <cuda_runtime.h>
#include <math.h>

// ---------------------------------------------------------------------------
// ZBLRepulsion: per-edge repulsion energy + segment_sum over receivers.
//   N_NODES = 1,000,000   N_EDGES = 32,000,000   N_SPECIES = 100
//
// Converged design (best measured 334.8us; replicate 340.9us — ±3us @NAT):
//   prep : params + 100-entry species table (block 0); species->u8 pack;
//          zero output.  (2 launches/call)
//   edge : 4 edges/thread (empirical MLP optimum at exactly 32 regs /
//          64-warp occupancy), float4/int4 L2-streaming loads, 8 batched
//          random u8 species gathers (1MB table, L1-cached ~22%), smem
//          species->{z, d*z^p} resolve, RED.ADD scatter.
//
// Floor model (validated R3-R7): l1tex wavefronts bind —
//   64M random gather lanes + 32M spread REDG + 4M streaming ≈ 676K cyc/SM,
//   L1=87% / L2=89% co-saturated. All structural alternatives (sorting,
//   binned scatter, DSMEM cluster table, edge-precompute, sub-byte packing)
//   re-spend the wavefronts they save. Micro-change this round: issue each
//   RED as soon as its value is ready (overlap REDs with remaining MUFU).
// ---------------------------------------------------------------------------

#define KE_CONST 14.399645351950548
#define MAX_NODES   1000000
#define MAX_SPECIES 128

__device__ float  g_params[8];                      // a0..a3, c0..3 (*KE/2)
__device__ float2 g_stab[MAX_SPECIES];              // per-species {z, d*z^p}
__device__ uchar4 g_spec4[(MAX_NODES + 3) / 4];     // packed species bytes

__device__ __forceinline__ float softplus_f(float x) {
    return fmaxf(x, 0.0f) + log1pf(expf(-fabsf(x)));
}

// ---- kernel 0: fused prep (params+table in block 0; pack+zero everywhere) --
__global__ void zbl_prep_kernel(const float* __restrict__ a_raw,
                                const float* __restrict__ c_raw,
                                const float* __restrict__ p_raw,
                                const float* __restrict__ d_raw,
                                const int* __restrict__ index_to_z,
                                const int* __restrict__ species,
                                float* __restrict__ out,
                                int n_species, int n_nodes, int out_n) {
    if (blockIdx.x == 0) {
        int t = threadIdx.x;
        if (t < n_species) {
            float p  = softplus_f(p_raw[0]);
            float d  = softplus_f(d_raw[0]);
            float zf = (float)index_to_z[t];
            g_stab[t] = make_float2(zf, d * powf(zf, p));
        }
        if (t == 0) {
            float c[4], csum = 0.0f;
#pragma unroll
            for (int k = 0; k < 4; k++) {
                g_params[k] = softplus_f(a_raw[k]);
                c[k] = softplus_f(c_raw[k]);
                csum += c[k];
            }
            float scale = (float)(KE_CONST * 0.5) / csum;
#pragma unroll
            for (int k = 0; k < 4; k++) g_params[4 + k] = c[k] * scale;
        }
    }

    int q = blockIdx.x * blockDim.x + threadIdx.x;
    int base = q * 4;
    if (base + 3 < n_nodes) {
        int4 s = *reinterpret_cast<const int4*>(species + base);
        g_spec4[q] = make_uchar4((unsigned char)s.x, (unsigned char)s.y,
                                 (unsigned char)s.z, (unsigned char)s.w);
    } else if (base < n_nodes) {
        unsigned char* sp = reinterpret_cast<unsigned char*>(g_spec4);
        for (int k = base; k < n_nodes; k++) sp[k] = (unsigned char)species[k];
    }
    if (base + 3 < out_n) {
        *reinterpret_cast<float4*>(out + base) = make_float4(0.f, 0.f, 0.f, 0.f);
    } else if (base < out_n) {
        for (int k = base; k < out_n; k++) out[k] = 0.0f;
    }
}

// ---- per-edge math --------------------------------------------------------
__device__ __forceinline__ float zbl_energy(float dd, float ct,
                                            unsigned int si, unsigned int ri,
                                            const float* __restrict__ P,
                                            const float2* __restrict__ stab) {
    float2 nj = stab[si];
    float2 ni = stab[ri];

    float x   = ct * ni.x * nj.x * __fdividef(1.0f, dd + 1e-8f);
    float rzd = dd * (ni.y + nj.y);

    float y = P[4] * __expf(-P[0] * rzd)
            + P[5] * __expf(-P[1] * rzd)
            + P[6] * __expf(-P[2] * rzd)
            + P[7] * __expf(-P[3] * rzd);

    float sd = dd * (1.0f / 1.5f);
    float e1 = __expf(-__fdividef(1.0f, fmaxf(sd, 1e-8f)));
    float e2 = __expf(-__fdividef(1.0f, fmaxf(1.0f - sd, 1e-8f)));
    float w  = __fdividef(e2, e1 + e2);

    return w * x * y;
}

// ---- kernel 1: edge loop, 4 edges/thread (empirical optimum, 32 regs) -----
__global__ void __launch_bounds__(256)
zbl_edge_kernel(const float* __restrict__ distances,
                const float* __restrict__ cutoffs,
                const int* __restrict__ senders,
                const int* __restrict__ receivers,
                float* __restrict__ out,
                int n_edges, int n_species) {
    __shared__ float2 stab[MAX_SPECIES];
    for (int t = threadIdx.x; t < n_species; t += blockDim.x)
        stab[t] = g_stab[t];
    float P[8];
#pragma unroll
    for (int k = 0; k < 8; k++) P[k] = g_params[k];
    __syncthreads();

    const unsigned char* spec = reinterpret_cast<const unsigned char*>(g_spec4);

    int i  = blockIdx.x * blockDim.x + threadIdx.x;
    long long e0 = (long long)i * 4;
    if (e0 >= n_edges) return;

    if (e0 + 3 < n_edges) {
        // streaming loads: L2-only, keep L1 for the species gathers
        float4 d4 = __ldcg(reinterpret_cast<const float4*>(distances + e0));
        float4 c4 = __ldcg(reinterpret_cast<const float4*>(cutoffs   + e0));
        int4   s4 = __ldcg(reinterpret_cast<const int4*>(senders    + e0));
        int4   r4 = __ldcg(reinterpret_cast<const int4*>(receivers  + e0));

        // all 8 gathers in flight before compute
        unsigned int sa = __ldg(spec + s4.x), ra = __ldg(spec + r4.x);
        unsigned int sb = __ldg(spec + s4.y), rb = __ldg(spec + r4.y);
        unsigned int sc = __ldg(spec + s4.z), rc = __ldg(spec + r4.z);
        unsigned int sd_ = __ldg(spec + s4.w), rd = __ldg(spec + r4.w);

        // compute + fire each RED as soon as its value is ready
        float va = zbl_energy(d4.x, c4.x, sa, ra, P, stab);
        atomicAdd(out + r4.x, va);
        float vb = zbl_energy(d4.y, c4.y, sb, rb, P, stab);
        atomicAdd(out + r4.y, vb);
        float vc = zbl_energy(d4.z, c4.z, sc, rc, P, stab);
        atomicAdd(out + r4.z, vc);
        float vd = zbl_energy(d4.w, c4.w, sd_, rd, P, stab);
        atomicAdd(out + r4.w, vd);
    } else {
        for (long long e = e0; e < n_edges; e++) {
            unsigned int si = spec[senders[e]];
            unsigned int ri = spec[receivers[e]];
            float v = zbl_energy(distances[e], cutoffs[e], si, ri, P, stab);
            atomicAdd(out + receivers[e], v);
        }
    }
}

// ---------------------------------------------------------------------------
extern "C" void kernel_launch(void* const* d_in, const int* in_sizes, int n_in,
                              void* d_out, int out_size) {
    const int*   node_species = (const int*)  d_in[0];
    const float* distances    = (const float*)d_in[1];
    const float* cutoffs      = (const float*)d_in[2];
    const int*   senders      = (const int*)  d_in[3];
    const int*   receivers    = (const int*)  d_in[4];
    const int*   index_to_z   = (const int*)  d_in[5];
    const float* a_raw        = (const float*)d_in[6];
    const float* c_raw        = (const float*)d_in[7];
    const float* p_raw        = (const float*)d_in[8];
    const float* d_raw        = (const float*)d_in[9];

    int n_nodes   = in_sizes[0];
    int n_edges   = in_sizes[1];
    int n_species = in_sizes[5];
    float* out    = (float*)d_out;

    {
        int n = (n_nodes > out_size) ? n_nodes : out_size;
        int quads   = (n + 3) / 4;
        int threads = 256;
        int blocks  = (quads + threads - 1) / threads;
        zbl_prep_kernel<<<blocks, threads>>>(a_raw, c_raw, p_raw, d_raw,
                                             index_to_z, node_species, out,
                                             n_species, n_nodes, out_size);
    }

    {
        int threads = 256;
        long long quads = ((long long)n_edges + 3) / 4;
        int blocks  = (int)((quads + threads - 1) / threads);
        zbl_edge_kernel<<<blocks, threads>>>(distances, cutoffs, senders,
                                             receivers, out, n_edges,
                                             n_species);
    }
}

// round 9
// speedup vs baseline: 1.1250x; 1.0243x over previous
#include <cuda_runtime.h>
#include <math.h>

// ---------------------------------------------------------------------------
// ZBLRepulsion: per-edge repulsion energy + segment_sum over receivers.
//   N_NODES = 1,000,000   N_EDGES = 32,000,000   N_SPECIES = 100
//
// Converged design:
//   prep : params + 100-entry species table (block 0); species->u8 pack;
//          zero output. 8 nodes/thread, 512-thread blocks (tail-trimmed).
//   edge : 4 edges/thread (MLP optimum at exactly 32 regs / 64-warp occ),
//          float4/int4 L2-streaming loads, 8 batched random u8 species
//          gathers (1MB table, L1 ~22% hit), smem {z, d*z^p} resolve,
//          EARLY RED.ADD (fire each RED as soon as its value is ready —
//          validated win: edge 337.5 -> 328.2us, L1 87->89.5%).
//
// Floor model (validated R3-R8): l1tex wavefronts bind — 64M random gather
// lanes + 32M spread REDG + 4M streaming ≈ 676K cyc/SM, L1/L2 ~90%
// co-saturated. Structural alternatives (sorting, binned scatter, DSMEM
// cluster table, edge-precompute, sub-byte packing) re-spend the wavefronts
// they save. Remaining margin is the prep launch gap (~8us) — trimmed here.
// ---------------------------------------------------------------------------

#define KE_CONST 14.399645351950548
#define MAX_NODES   1000000
#define MAX_SPECIES 128

__device__ float  g_params[8];                      // a0..a3, c0..3 (*KE/2)
__device__ float2 g_stab[MAX_SPECIES];              // per-species {z, d*z^p}
__device__ uchar4 g_spec4[(MAX_NODES + 3) / 4];     // packed species bytes

__device__ __forceinline__ float softplus_f(float x) {
    return fmaxf(x, 0.0f) + log1pf(expf(-fabsf(x)));
}

// ---- kernel 0: fused prep (params+table in block 0; pack+zero, 8/thread) --
__global__ void __launch_bounds__(512)
zbl_prep_kernel(const float* __restrict__ a_raw,
                const float* __restrict__ c_raw,
                const float* __restrict__ p_raw,
                const float* __restrict__ d_raw,
                const int* __restrict__ index_to_z,
                const int* __restrict__ species,
                float* __restrict__ out,
                int n_species, int n_nodes, int out_n) {
    if (blockIdx.x == 0) {
        int t = threadIdx.x;
        if (t < n_species) {
            float p  = softplus_f(p_raw[0]);
            float d  = softplus_f(d_raw[0]);
            float zf = (float)index_to_z[t];
            g_stab[t] = make_float2(zf, d * powf(zf, p));
        }
        if (t == 0) {
            float c[4], csum = 0.0f;
#pragma unroll
            for (int k = 0; k < 4; k++) {
                g_params[k] = softplus_f(a_raw[k]);
                c[k] = softplus_f(c_raw[k]);
                csum += c[k];
            }
            float scale = (float)(KE_CONST * 0.5) / csum;
#pragma unroll
            for (int k = 0; k < 4; k++) g_params[4 + k] = c[k] * scale;
        }
    }

    int i = blockIdx.x * blockDim.x + threadIdx.x;
    long long base = (long long)i * 8;      // 8 nodes per thread

    // pack species -> u8 (two uchar4 stores)
    if (base + 7 < n_nodes) {
        int4 s0 = *reinterpret_cast<const int4*>(species + base);
        int4 s1 = *reinterpret_cast<const int4*>(species + base + 4);
        g_spec4[(base >> 2) + 0] =
            make_uchar4((unsigned char)s0.x, (unsigned char)s0.y,
                        (unsigned char)s0.z, (unsigned char)s0.w);
        g_spec4[(base >> 2) + 1] =
            make_uchar4((unsigned char)s1.x, (unsigned char)s1.y,
                        (unsigned char)s1.z, (unsigned char)s1.w);
    } else if (base < n_nodes) {
        unsigned char* sp = reinterpret_cast<unsigned char*>(g_spec4);
        for (long long k = base; k < n_nodes; k++)
            sp[k] = (unsigned char)species[k];
    }

    // zero output (two float4 stores)
    if (base + 7 < out_n) {
        float4 z = make_float4(0.f, 0.f, 0.f, 0.f);
        *reinterpret_cast<float4*>(out + base)     = z;
        *reinterpret_cast<float4*>(out + base + 4) = z;
    } else if (base < out_n) {
        for (long long k = base; k < out_n; k++) out[k] = 0.0f;
    }
}

// ---- per-edge math --------------------------------------------------------
__device__ __forceinline__ float zbl_energy(float dd, float ct,
                                            unsigned int si, unsigned int ri,
                                            const float* __restrict__ P,
                                            const float2* __restrict__ stab) {
    float2 nj = stab[si];
    float2 ni = stab[ri];

    float x   = ct * ni.x * nj.x * __fdividef(1.0f, dd + 1e-8f);
    float rzd = dd * (ni.y + nj.y);

    float y = P[4] * __expf(-P[0] * rzd)
            + P[5] * __expf(-P[1] * rzd)
            + P[6] * __expf(-P[2] * rzd)
            + P[7] * __expf(-P[3] * rzd);

    float sd = dd * (1.0f / 1.5f);
    float e1 = __expf(-__fdividef(1.0f, fmaxf(sd, 1e-8f)));
    float e2 = __expf(-__fdividef(1.0f, fmaxf(1.0f - sd, 1e-8f)));
    float w  = __fdividef(e2, e1 + e2);

    return w * x * y;
}

// ---- kernel 1: edge loop, 4 edges/thread, early REDs (R8, unchanged) ------
__global__ void __launch_bounds__(256)
zbl_edge_kernel(const float* __restrict__ distances,
                const float* __restrict__ cutoffs,
                const int* __restrict__ senders,
                const int* __restrict__ receivers,
                float* __restrict__ out,
                int n_edges, int n_species) {
    __shared__ float2 stab[MAX_SPECIES];
    for (int t = threadIdx.x; t < n_species; t += blockDim.x)
        stab[t] = g_stab[t];
    float P[8];
#pragma unroll
    for (int k = 0; k < 8; k++) P[k] = g_params[k];
    __syncthreads();

    const unsigned char* spec = reinterpret_cast<const unsigned char*>(g_spec4);

    int i  = blockIdx.x * blockDim.x + threadIdx.x;
    long long e0 = (long long)i * 4;
    if (e0 >= n_edges) return;

    if (e0 + 3 < n_edges) {
        // streaming loads: L2-only, keep L1 for the species gathers
        float4 d4 = __ldcg(reinterpret_cast<const float4*>(distances + e0));
        float4 c4 = __ldcg(reinterpret_cast<const float4*>(cutoffs   + e0));
        int4   s4 = __ldcg(reinterpret_cast<const int4*>(senders    + e0));
        int4   r4 = __ldcg(reinterpret_cast<const int4*>(receivers  + e0));

        // all 8 gathers in flight before compute
        unsigned int sa = __ldg(spec + s4.x), ra = __ldg(spec + r4.x);
        unsigned int sb = __ldg(spec + s4.y), rb = __ldg(spec + r4.y);
        unsigned int sc = __ldg(spec + s4.z), rc = __ldg(spec + r4.z);
        unsigned int sd_ = __ldg(spec + s4.w), rd = __ldg(spec + r4.w);

        // compute + fire each RED as soon as its value is ready
        float va = zbl_energy(d4.x, c4.x, sa, ra, P, stab);
        atomicAdd(out + r4.x, va);
        float vb = zbl_energy(d4.y, c4.y, sb, rb, P, stab);
        atomicAdd(out + r4.y, vb);
        float vc = zbl_energy(d4.z, c4.z, sc, rc, P, stab);
        atomicAdd(out + r4.z, vc);
        float vd = zbl_energy(d4.w, c4.w, sd_, rd, P, stab);
        atomicAdd(out + r4.w, vd);
    } else {
        for (long long e = e0; e < n_edges; e++) {
            unsigned int si = spec[senders[e]];
            unsigned int ri = spec[receivers[e]];
            float v = zbl_energy(distances[e], cutoffs[e], si, ri, P, stab);
            atomicAdd(out + receivers[e], v);
        }
    }
}

// ---------------------------------------------------------------------------
extern "C" void kernel_launch(void* const* d_in, const int* in_sizes, int n_in,
                              void* d_out, int out_size) {
    const int*   node_species = (const int*)  d_in[0];
    const float* distances    = (const float*)d_in[1];
    const float* cutoffs      = (const float*)d_in[2];
    const int*   senders      = (const int*)  d_in[3];
    const int*   receivers    = (const int*)  d_in[4];
    const int*   index_to_z   = (const int*)  d_in[5];
    const float* a_raw        = (const float*)d_in[6];
    const float* c_raw        = (const float*)d_in[7];
    const float* p_raw        = (const float*)d_in[8];
    const float* d_raw        = (const float*)d_in[9];

    int n_nodes   = in_sizes[0];
    int n_edges   = in_sizes[1];
    int n_species = in_sizes[5];
    float* out    = (float*)d_out;

    {
        int n = (n_nodes > out_size) ? n_nodes : out_size;
        long long octs = ((long long)n + 7) / 8;
        int threads = 512;
        int blocks  = (int)((octs + threads - 1) / threads);
        zbl_prep_kernel<<<blocks, threads>>>(a_raw, c_raw, p_raw, d_raw,
                                             index_to_z, node_species, out,
                                             n_species, n_nodes, out_size);
    }

    {
        int threads = 256;
        long long quads = ((long long)n_edges + 3) / 4;
        int blocks  = (int)((quads + threads - 1) / threads);
        zbl_edge_kernel<<<blocks, threads>>>(distances, cutoffs, senders,
                                             receivers, out, n_edges,
                                             n_species);
    }
}